// round 8
// baseline (speedup 1.0000x reference)
#include <cuda_runtime.h>
#include <cuda_fp16.h>
#include <math.h>

// ---------------- problem constants ----------------
#define MAX_NODES 50000

// scatter-order fp16 records: per lane 20 halves = uint4 + uint4 + uint2 (40B)
__device__ uint4 g_nodeA[MAX_NODES * 32];
__device__ uint4 g_nodeB[MAX_NODES * 32];
__device__ uint2 g_nodeC[MAX_NODES * 32];

// ---- constants derived from the reference's (non-standard) CG formula ----
#define ALPHA0 0.125f
#define ALPHA1 0.10206207261596575f
#define D0 0.6666666666666666f
#define D1 0.3333333333333333f
#define E0 0.6963106238227914f
#define E1 0.17407765595569785f
#define N1 0.48888007f
#define N2 0.04704256f
#define N3 0.06111001f
#define N4 0.12222002f

#define NPW 4   // nodes per warp in precompute

static __device__ __forceinline__ unsigned pack2(float a, float b) {
    half2 h = __floats2half2_rn(a, b);
    return *reinterpret_cast<unsigned*>(&h);
}
static __device__ __forceinline__ float2 unpack2(unsigned u) {
    half2 h = *reinterpret_cast<half2*>(&u);
    return __half22float2(h);
}

// ---------------- per-node precompute: 4 nodes/warp, lane = channel; pack scatter-order ----------------
__global__ void __launch_bounds__(256) precompute_kernel(const float* __restrict__ feat,
                                                         const float* __restrict__ W,
                                                         int n_nodes) {
    __shared__ float Ws[5 * 1024];
    __shared__ float4 xs[8][NPW * 32];   // staging; reused as chbuf after the u-loop

    for (int i = threadIdx.x; i < 5 * 1024; i += blockDim.x) {
        int p = i >> 10;
        float s = (p == 0 || p == 3) ? ALPHA0 : ALPHA1;
        Ws[i] = s * W[i];
    }
    __syncthreads();

    int lane = threadIdx.x & 31;
    int wl   = threadIdx.x >> 5;
    int warp = (blockIdx.x * blockDim.x + threadIdx.x) >> 5;
    int nwarp = (gridDim.x * blockDim.x) >> 5;

    for (int nb = warp * NPW; nb < n_nodes; nb += nwarp * NPW) {
        // stage NPW nodes' inputs: float4(x0[u], y0[u], y1[u], y2[u]), u = lane
        #pragma unroll
        for (int nn = 0; nn < NPW; nn++) {
            int n = nb + nn;
            float4 v = make_float4(0.f, 0.f, 0.f, 0.f);
            if (n < n_nodes) {
                const float* x = feat + (size_t)n * 128;
                v.x = x[lane];
                v.y = x[32 + 3 * lane];
                v.z = x[33 + 3 * lane];
                v.w = x[34 + 3 * lane];
            }
            xs[wl][nn * 32 + lane] = v;
        }
        __syncwarp();

        float a1[NPW], a2[NPW], b3[NPW][3], b4[NPW][3], b5[NPW][3];
        #pragma unroll
        for (int nn = 0; nn < NPW; nn++) {
            a1[nn] = 0.f; a2[nn] = 0.f;
            #pragma unroll
            for (int k = 0; k < 3; k++) { b3[nn][k] = 0.f; b4[nn][k] = 0.f; b5[nn][k] = 0.f; }
        }

        #pragma unroll 4
        for (int u = 0; u < 32; u++) {
            float w0 = Ws[          u * 32 + lane];
            float w1 = Ws[1024 +    u * 32 + lane];
            float w2 = Ws[2048 +    u * 32 + lane];
            float w3 = Ws[3072 +    u * 32 + lane];
            float w4 = Ws[4096 +    u * 32 + lane];
            #pragma unroll
            for (int nn = 0; nn < NPW; nn++) {
                float4 v = xs[wl][nn * 32 + u];   // broadcast
                a1[nn] = fmaf(v.x, w0, a1[nn]);
                a2[nn] = fmaf(v.x, w1, a2[nn]);
                b3[nn][0] = fmaf(v.y, w2, b3[nn][0]);
                b3[nn][1] = fmaf(v.z, w2, b3[nn][1]);
                b3[nn][2] = fmaf(v.w, w2, b3[nn][2]);
                b4[nn][0] = fmaf(v.y, w3, b4[nn][0]);
                b4[nn][1] = fmaf(v.z, w3, b4[nn][1]);
                b4[nn][2] = fmaf(v.w, w3, b4[nn][2]);
                b5[nn][0] = fmaf(v.y, w4, b5[nn][0]);
                b5[nn][1] = fmaf(v.z, w4, b5[nn][1]);
                b5[nn][2] = fmaf(v.w, w4, b5[nn][2]);
            }
        }
        __syncwarp();   // done reading xs as staging

        // per node: stage channel-order values in SMEM, pack scatter-order record
        float* chb = (float*)&xs[wl][0];   // 512 floats available; need 32*12
        #pragma unroll
        for (int nn = 0; nn < NPW; nn++) {
            int n = nb + nn;
            if (n >= n_nodes) break;
            chb[lane * 12 + 0]  = a1[nn];
            chb[lane * 12 + 1]  = a2[nn];
            chb[lane * 12 + 2]  = b3[nn][0] * D0;
            chb[lane * 12 + 3]  = b3[nn][1] * D1;
            chb[lane * 12 + 4]  = b3[nn][2] * D0;
            chb[lane * 12 + 5]  = b4[nn][0] * E0;
            chb[lane * 12 + 6]  = b4[nn][1] * E1;
            chb[lane * 12 + 7]  = b4[nn][2] * E0;
            chb[lane * 12 + 8]  = b5[nn][0];
            chb[lane * 12 + 9]  = b5[nn][1];
            chb[lane * 12 + 10] = b5[nn][2];
            __syncwarp();

            uint4 RA, RB;
            uint2 RC = make_uint2(0, 0);
            if (lane < 8) {
                // lanes 0..7: out0 channels c = 4*lane + j; need a1[c], b4'[c][0..2]
                float A[4], Bx[4], By[4], Bz[4];
                #pragma unroll
                for (int j = 0; j < 4; j++) {
                    int c = 4 * lane + j;
                    A[j]  = chb[c * 12 + 0];
                    Bx[j] = chb[c * 12 + 5];
                    By[j] = chb[c * 12 + 6];
                    Bz[j] = chb[c * 12 + 7];
                }
                RA.x = pack2(A[0], Bx[0]); RA.y = pack2(By[0], Bz[0]);
                RA.z = pack2(A[1], Bx[1]); RA.w = pack2(By[1], Bz[1]);
                RB.x = pack2(A[2], Bx[2]); RB.y = pack2(By[2], Bz[2]);
                RB.z = pack2(A[3], Bx[3]); RB.w = pack2(By[3], Bz[3]);
            } else {
                // lanes 8..31: out1 positions q = 4*(lane-8)+j; w=q/3, k=q%3
                float ca[4], cb[4], fx[4], fy[4], fz[4];
                #pragma unroll
                for (int j = 0; j < 4; j++) {
                    int q = 4 * (lane - 8) + j;
                    int w = q / 3;
                    int k = q - 3 * w;
                    float Dk = (k == 1) ? D1 : D0;
                    ca[j] = Dk * chb[w * 12 + 1];       // D-folded a2[w]
                    cb[j] = chb[w * 12 + 2 + k];        // D-folded b3[w][k]
                    fx[j] = chb[w * 12 + 8];
                    fy[j] = chb[w * 12 + 9];
                    fz[j] = chb[w * 12 + 10];
                }
                RA.x = pack2(ca[0], cb[0]); RA.y = pack2(ca[1], cb[1]);
                RA.z = pack2(ca[2], cb[2]); RA.w = pack2(ca[3], cb[3]);
                RB.x = pack2(fx[0], fy[0]); RB.y = pack2(fz[0], fx[1]);
                RB.z = pack2(fy[1], fz[1]); RB.w = pack2(fx[2], fy[2]);
                RC.x = pack2(fz[2], fx[3]); RC.y = pack2(fy[3], fz[3]);
            }
            g_nodeA[n * 32 + lane] = RA;
            g_nodeB[n * 32 + lane] = RB;
            g_nodeC[n * 32 + lane] = RC;
            __syncwarp();
        }
    }
}

// ---------------- per-edge: gather scatter-order record, compute 4 outputs/lane, red.v4 ----------------
__global__ void __launch_bounds__(256) edge_kernel(const float* __restrict__ sh,
                                                   const int* __restrict__ eidx,
                                                   float* __restrict__ out,
                                                   int n_edges) {
    const unsigned FULL = 0xFFFFFFFFu;
    int lane  = threadIdx.x & 31;
    int warp  = (blockIdx.x * blockDim.x + threadIdx.x) >> 5;
    int nwarp = (gridDim.x * blockDim.x) >> 5;
    bool grpA = (lane < 8);

    // loop-invariant select predicates for grpB lanes
    bool k0[4], k1[4];
    {
        int qb = 4 * (lane - 8);
        #pragma unroll
        for (int j = 0; j < 4; j++) {
            int q = qb + j;
            int kj = ((q % 3) + 3) % 3;
            k0[j] = (kj == 0);
            k1[j] = (kj == 1);
        }
    }

    int e = warp;
    int src = 0, dst = 0;
    float sv = 0.f;
    if (e < n_edges) {
        src = eidx[e];
        dst = eidx[n_edges + e];
        sv  = (lane < 9) ? sh[(size_t)e * 9 + lane] : 0.f;
    }

    while (e < n_edges) {
        // gather record for current edge (issued first, deepest latency)
        uint4 RA = g_nodeA[src * 32 + lane];
        uint4 RB = g_nodeB[src * 32 + lane];
        uint2 RC = g_nodeC[src * 32 + lane];

        // prefetch next edge's idx + sh while the gather is in flight
        int en = e + nwarp;
        int nsrc = 0, ndst = 0;
        float nsv = 0.f;
        if (en < n_edges) {
            nsrc = eidx[en];
            ndst = eidx[n_edges + en];
            nsv  = (lane < 9) ? sh[(size_t)en * 9 + lane] : 0.f;
        }

        // broadcast sh components
        float s0  = __shfl_sync(FULL, sv, 0);
        float s1x = __shfl_sync(FULL, sv, 1);
        float s1y = __shfl_sync(FULL, sv, 2);
        float s1z = __shfl_sync(FULL, sv, 3);
        float q0  = __shfl_sync(FULL, sv, 4);
        float q1v = __shfl_sync(FULL, sv, 5);
        float q2  = __shfl_sync(FULL, sv, 6);
        float q3  = __shfl_sync(FULL, sv, 7);
        float q4  = __shfl_sync(FULL, sv, 8);

        // S rows (l=2 path contraction), k = out component
        float n2q2 = N2 * q2;
        float n1q4 = N1 * q4;
        float n1q0 = N1 * q0;
        float S00 = -(n2q2 + n1q4), S01 = N3 * q1v, S02 = n1q0;
        float S10 = N4 * q1v,       S11 = n2q2,     S12 = N4 * q3;
        float S20 = n1q0,           S21 = N3 * q3,  S22 = n1q4 - n2q2;

        float v[4];
        if (grpA) {
            float2 p0 = unpack2(RA.x), p1 = unpack2(RA.y);
            float2 p2 = unpack2(RA.z), p3 = unpack2(RA.w);
            float2 p4 = unpack2(RB.x), p5 = unpack2(RB.y);
            float2 p6 = unpack2(RB.z), p7 = unpack2(RB.w);
            v[0] = fmaf(s0, p0.x, fmaf(s1x, p0.y, fmaf(s1y, p1.x, s1z * p1.y)));
            v[1] = fmaf(s0, p2.x, fmaf(s1x, p2.y, fmaf(s1y, p3.x, s1z * p3.y)));
            v[2] = fmaf(s0, p4.x, fmaf(s1x, p4.y, fmaf(s1y, p5.x, s1z * p5.y)));
            v[3] = fmaf(s0, p6.x, fmaf(s1x, p6.y, fmaf(s1y, p7.x, s1z * p7.y)));
        } else {
            float2 p0 = unpack2(RA.x), p1 = unpack2(RA.y);
            float2 p2 = unpack2(RA.z), p3 = unpack2(RA.w);
            float ca[4] = { p0.x, p1.x, p2.x, p3.x };
            float cb[4] = { p0.y, p1.y, p2.y, p3.y };
            float2 q0p = unpack2(RB.x), q1p = unpack2(RB.y);
            float2 q2p = unpack2(RB.z), q3p = unpack2(RB.w);
            float2 r0p = unpack2(RC.x), r1p = unpack2(RC.y);
            float fx[4] = { q0p.x, q1p.y, q3p.x, r0p.y };
            float fy[4] = { q0p.y, q2p.x, q3p.y, r1p.x };
            float fz[4] = { q1p.x, q2p.y, r0p.x, r1p.y };
            #pragma unroll
            for (int j = 0; j < 4; j++) {
                float s1s = k0[j] ? s1x : (k1[j] ? s1y : s1z);
                float Sa  = k0[j] ? S00 : (k1[j] ? S10 : S20);
                float Sb  = k0[j] ? S01 : (k1[j] ? S11 : S21);
                float Sc  = k0[j] ? S02 : (k1[j] ? S12 : S22);
                v[j] = fmaf(s1s, ca[j],
                       fmaf(s0, cb[j],
                       fmaf(Sa, fx[j],
                       fmaf(Sb, fy[j], Sc * fz[j]))));
            }
        }

        float* dptr = out + (size_t)dst * 128 + 4 * lane;
        asm volatile("red.global.add.v4.f32 [%0], {%1,%2,%3,%4};"
                     :: "l"(dptr), "f"(v[0]), "f"(v[1]), "f"(v[2]), "f"(v[3]) : "memory");

        e = en; src = nsrc; dst = ndst; sv = nsv;
    }
}

// ---------------- launch ----------------
extern "C" void kernel_launch(void* const* d_in, const int* in_sizes, int n_in,
                              void* d_out, int out_size) {
    const float* feat = (const float*)d_in[0];
    const float* sh   = (const float*)d_in[1];
    const int*   eidx = (const int*)d_in[2];
    const float* W    = (const float*)d_in[3];
    int n_nodes = in_sizes[0] / 128;
    int n_edges = in_sizes[2] / 2;

    cudaMemsetAsync(d_out, 0, (size_t)out_size * sizeof(float));

    int warps_needed = (n_nodes + NPW - 1) / NPW;
    int pre_blocks = (warps_needed + 7) / 8;
    precompute_kernel<<<pre_blocks, 256>>>(feat, W, n_nodes);
    edge_kernel<<<2048, 256>>>(sh, eidx, (float*)d_out, n_edges);
}

// round 9
// speedup vs baseline: 1.1617x; 1.1617x over previous
#include <cuda_runtime.h>
#include <cuda_fp16.h>
#include <math.h>

// ---------------- problem constants ----------------
#define MAX_NODES 50000

// fp16-compressed per-node records (channel order): per lane 12 halves = uint4 + uint2 (24B)
__device__ uint4 g_node4[MAX_NODES * 32];
__device__ uint2 g_node2[MAX_NODES * 32];

// ---- constants derived from the reference's (non-standard) CG formula ----
#define ALPHA0 0.125f
#define ALPHA1 0.10206207261596575f
#define D0 0.6666666666666666f
#define D1 0.3333333333333333f
#define E0 0.6963106238227914f
#define E1 0.17407765595569785f
#define N1 0.48888007f
#define N2 0.04704256f
#define N3 0.06111001f
#define N4 0.12222002f

#define NPW 4   // nodes per warp in precompute

static __device__ __forceinline__ unsigned pack2(float a, float b) {
    half2 h = __floats2half2_rn(a, b);
    return *reinterpret_cast<unsigned*>(&h);
}
static __device__ __forceinline__ float2 unpack2(unsigned u) {
    half2 h = *reinterpret_cast<half2*>(&u);
    return __half22float2(h);
}

// ---------------- per-node precompute: 4 nodes/warp, lane = channel ----------------
__global__ void __launch_bounds__(256) precompute_kernel(const float* __restrict__ feat,
                                                         const float* __restrict__ W,
                                                         int n_nodes) {
    __shared__ float Ws[5 * 1024];
    __shared__ float4 xs[8][NPW * 32];   // per-warp staging: [warp][nn*32+u] = (x0,y0,y1,y2)

    for (int i = threadIdx.x; i < 5 * 1024; i += blockDim.x) {
        int p = i >> 10;
        float s = (p == 0 || p == 3) ? ALPHA0 : ALPHA1;
        Ws[i] = s * W[i];
    }
    __syncthreads();

    int lane = threadIdx.x & 31;
    int wl   = threadIdx.x >> 5;
    int warp = (blockIdx.x * blockDim.x + threadIdx.x) >> 5;
    int nwarp = (gridDim.x * blockDim.x) >> 5;

    for (int nb = warp * NPW; nb < n_nodes; nb += nwarp * NPW) {
        #pragma unroll
        for (int nn = 0; nn < NPW; nn++) {
            int n = nb + nn;
            float4 v = make_float4(0.f, 0.f, 0.f, 0.f);
            if (n < n_nodes) {
                const float* x = feat + (size_t)n * 128;
                v.x = x[lane];
                v.y = x[32 + 3 * lane];
                v.z = x[33 + 3 * lane];
                v.w = x[34 + 3 * lane];
            }
            xs[wl][nn * 32 + lane] = v;
        }
        __syncwarp();

        float a1[NPW], a2[NPW], b3[NPW][3], b4[NPW][3], b5[NPW][3];
        #pragma unroll
        for (int nn = 0; nn < NPW; nn++) {
            a1[nn] = 0.f; a2[nn] = 0.f;
            #pragma unroll
            for (int k = 0; k < 3; k++) { b3[nn][k] = 0.f; b4[nn][k] = 0.f; b5[nn][k] = 0.f; }
        }

        #pragma unroll 4
        for (int u = 0; u < 32; u++) {
            float w0 = Ws[          u * 32 + lane];
            float w1 = Ws[1024 +    u * 32 + lane];
            float w2 = Ws[2048 +    u * 32 + lane];
            float w3 = Ws[3072 +    u * 32 + lane];
            float w4 = Ws[4096 +    u * 32 + lane];
            #pragma unroll
            for (int nn = 0; nn < NPW; nn++) {
                float4 v = xs[wl][nn * 32 + u];   // broadcast (all lanes same addr)
                a1[nn] = fmaf(v.x, w0, a1[nn]);
                a2[nn] = fmaf(v.x, w1, a2[nn]);
                b3[nn][0] = fmaf(v.y, w2, b3[nn][0]);
                b3[nn][1] = fmaf(v.z, w2, b3[nn][1]);
                b3[nn][2] = fmaf(v.w, w2, b3[nn][2]);
                b4[nn][0] = fmaf(v.y, w3, b4[nn][0]);
                b4[nn][1] = fmaf(v.z, w3, b4[nn][1]);
                b4[nn][2] = fmaf(v.w, w3, b4[nn][2]);
                b5[nn][0] = fmaf(v.y, w4, b5[nn][0]);
                b5[nn][1] = fmaf(v.z, w4, b5[nn][1]);
                b5[nn][2] = fmaf(v.w, w4, b5[nn][2]);
            }
        }

        #pragma unroll
        for (int nn = 0; nn < NPW; nn++) {
            int n = nb + nn;
            if (n >= n_nodes) break;
            float c30 = b3[nn][0] * D0, c31 = b3[nn][1] * D1, c32 = b3[nn][2] * D0;
            float c40 = b4[nn][0] * E0, c41 = b4[nn][1] * E1, c42 = b4[nn][2] * E0;
            uint4 p;
            p.x = pack2(a1[nn], a2[nn]);
            p.y = pack2(c30, c31);
            p.z = pack2(c32, c40);
            p.w = pack2(c41, c42);
            uint2 q;
            q.x = pack2(b5[nn][0], b5[nn][1]);
            q.y = pack2(b5[nn][2], 0.f);
            g_node4[n * 32 + lane] = p;
            g_node2[n * 32 + lane] = q;
        }
        __syncwarp();
    }
}

// ---------------- per-edge: uniform per-lane math, 4 scalar REDs (no transpose) ----------------
__global__ void __launch_bounds__(256) edge_kernel(const float* __restrict__ sh,
                                                   const int* __restrict__ eidx,
                                                   float* __restrict__ out,
                                                   int n_edges) {
    const unsigned FULL = 0xFFFFFFFFu;
    int lane  = threadIdx.x & 31;
    int warp  = (blockIdx.x * blockDim.x + threadIdx.x) >> 5;
    int nwarp = (gridDim.x * blockDim.x) >> 5;

    int e = warp;
    int src = 0, dst = 0;
    float sv = 0.f;
    if (e < n_edges) {
        src = eidx[e];
        dst = eidx[n_edges + e];
        sv  = (lane < 9) ? sh[(size_t)e * 9 + lane] : 0.f;
    }

    while (e < n_edges) {
        // issue record gather first (longest latency)
        uint4 rp = g_node4[src * 32 + lane];
        uint2 rq = g_node2[src * 32 + lane];

        // prefetch next edge's idx + sh while the gather is in flight
        int en = e + nwarp;
        int nsrc = 0, ndst = 0;
        float nsv = 0.f;
        if (en < n_edges) {
            nsrc = eidx[en];
            ndst = eidx[n_edges + en];
            nsv  = (lane < 9) ? sh[(size_t)en * 9 + lane] : 0.f;
        }

        // broadcast sh components
        float s0  = __shfl_sync(FULL, sv, 0);
        float s1x = __shfl_sync(FULL, sv, 1);
        float s1y = __shfl_sync(FULL, sv, 2);
        float s1z = __shfl_sync(FULL, sv, 3);
        float q0  = __shfl_sync(FULL, sv, 4);
        float q1v = __shfl_sync(FULL, sv, 5);
        float q2  = __shfl_sync(FULL, sv, 6);
        float q3  = __shfl_sync(FULL, sv, 7);
        float q4  = __shfl_sync(FULL, sv, 8);

        // path (1,2,1) sh-contraction terms
        float n2q2 = N2 * q2;
        float n1q4 = N1 * q4;
        float n1q0 = N1 * q0;
        float n3q1 = N3 * q1v;
        float n4q1 = N4 * q1v;
        float n3q3 = N3 * q3;
        float n4q3 = N4 * q3;

        float2 u0 = unpack2(rp.x);   // a1, a2
        float2 u1 = unpack2(rp.y);   // b3x, b3y
        float2 u2 = unpack2(rp.z);   // b3z, b4x
        float2 u3 = unpack2(rp.w);   // b4y, b4z
        float2 u4 = unpack2(rq.x);   // b5x, b5y
        float2 u5 = unpack2(rq.y);   // b5z, -
        float a1 = u0.x, a2 = u0.y;
        float b3x = u1.x, b3y = u1.y, b3z = u2.x;
        float b4x = u2.y, b4y = u3.x, b4z = u3.y;
        float b5x = u4.x, b5y = u4.y, b5z = u5.x;

        // out0: paths (0,0,0) and (1,1,0)
        float m0 = s0 * a1;
        m0 = fmaf(s1x, b4x, m0);
        m0 = fmaf(s1y, b4y, m0);
        m0 = fmaf(s1z, b4z, m0);

        // out1: paths (0,1,1), (1,0,1), (1,2,1)
        float m1x = fmaf(D0 * s1x, a2,
                    fmaf(s0, b3x,
                    fmaf(-(n2q2 + n1q4), b5x,
                    fmaf(n3q1, b5y, n1q0 * b5z))));
        float m1y = fmaf(D1 * s1y, a2,
                    fmaf(s0, b3y,
                    fmaf(n4q1, b5x,
                    fmaf(n2q2, b5y, n4q3 * b5z))));
        float m1z = fmaf(D0 * s1z, a2,
                    fmaf(s0, b3z,
                    fmaf(n1q0, b5x,
                    fmaf(n3q3, b5y, (n1q4 - n2q2) * b5z))));

        // scatter: lane l owns out0[l] and out1[w=l][k=0..2] -- uniform, no transpose
        float* base = out + (size_t)dst * 128;
        asm volatile("red.global.add.f32 [%0], %1;" :: "l"(base + lane),               "f"(m0)  : "memory");
        asm volatile("red.global.add.f32 [%0], %1;" :: "l"(base + 32 + 3 * lane),      "f"(m1x) : "memory");
        asm volatile("red.global.add.f32 [%0], %1;" :: "l"(base + 33 + 3 * lane),      "f"(m1y) : "memory");
        asm volatile("red.global.add.f32 [%0], %1;" :: "l"(base + 34 + 3 * lane),      "f"(m1z) : "memory");

        e = en; src = nsrc; dst = ndst; sv = nsv;
    }
}

// ---------------- launch ----------------
extern "C" void kernel_launch(void* const* d_in, const int* in_sizes, int n_in,
                              void* d_out, int out_size) {
    const float* feat = (const float*)d_in[0];
    const float* sh   = (const float*)d_in[1];
    const int*   eidx = (const int*)d_in[2];
    const float* W    = (const float*)d_in[3];
    int n_nodes = in_sizes[0] / 128;
    int n_edges = in_sizes[2] / 2;

    cudaMemsetAsync(d_out, 0, (size_t)out_size * sizeof(float));

    int warps_needed = (n_nodes + NPW - 1) / NPW;
    int pre_blocks = (warps_needed + 7) / 8;
    precompute_kernel<<<pre_blocks, 256>>>(feat, W, n_nodes);
    edge_kernel<<<2048, 256>>>(sh, eidx, (float*)d_out, n_edges);
}

// round 10
// speedup vs baseline: 1.4190x; 1.2215x over previous
#include <cuda_runtime.h>
#include <cuda_fp16.h>
#include <math.h>

// ---------------- problem constants ----------------
#define MAX_NODES 50000

// fp16-compressed per-node records (channel order): per lane 12 halves = uint4 + uint2 (24B)
__device__ uint4 g_node4[MAX_NODES * 32];
__device__ uint2 g_node2[MAX_NODES * 32];

// ---- constants derived from the reference's (non-standard) CG formula ----
#define ALPHA0 0.125f
#define ALPHA1 0.10206207261596575f
#define D0 0.6666666666666666f
#define D1 0.3333333333333333f
#define E0 0.6963106238227914f
#define E1 0.17407765595569785f
#define N1 0.48888007f
#define N2 0.04704256f
#define N3 0.06111001f
#define N4 0.12222002f

#define NPW 4   // nodes per warp in precompute

static __device__ __forceinline__ unsigned pack2(float a, float b) {
    half2 h = __floats2half2_rn(a, b);
    return *reinterpret_cast<unsigned*>(&h);
}
static __device__ __forceinline__ float2 unpack2(unsigned u) {
    half2 h = *reinterpret_cast<half2*>(&u);
    return __half22float2(h);
}

// ---------------- per-node precompute: 4 nodes/warp, lane = channel ----------------
__global__ void __launch_bounds__(256) precompute_kernel(const float* __restrict__ feat,
                                                         const float* __restrict__ W,
                                                         int n_nodes) {
    __shared__ float Ws[5 * 1024];
    __shared__ float4 xs[8][NPW * 32];   // per-warp staging: [warp][nn*32+u] = (x0,y0,y1,y2)

    for (int i = threadIdx.x; i < 5 * 1024; i += blockDim.x) {
        int p = i >> 10;
        float s = (p == 0 || p == 3) ? ALPHA0 : ALPHA1;
        Ws[i] = s * W[i];
    }
    __syncthreads();

    int lane = threadIdx.x & 31;
    int wl   = threadIdx.x >> 5;
    int warp = (blockIdx.x * blockDim.x + threadIdx.x) >> 5;
    int nwarp = (gridDim.x * blockDim.x) >> 5;

    for (int nb = warp * NPW; nb < n_nodes; nb += nwarp * NPW) {
        #pragma unroll
        for (int nn = 0; nn < NPW; nn++) {
            int n = nb + nn;
            float4 v = make_float4(0.f, 0.f, 0.f, 0.f);
            if (n < n_nodes) {
                const float* x = feat + (size_t)n * 128;
                v.x = x[lane];
                v.y = x[32 + 3 * lane];
                v.z = x[33 + 3 * lane];
                v.w = x[34 + 3 * lane];
            }
            xs[wl][nn * 32 + lane] = v;
        }
        __syncwarp();

        float a1[NPW], a2[NPW], b3[NPW][3], b4[NPW][3], b5[NPW][3];
        #pragma unroll
        for (int nn = 0; nn < NPW; nn++) {
            a1[nn] = 0.f; a2[nn] = 0.f;
            #pragma unroll
            for (int k = 0; k < 3; k++) { b3[nn][k] = 0.f; b4[nn][k] = 0.f; b5[nn][k] = 0.f; }
        }

        #pragma unroll 4
        for (int u = 0; u < 32; u++) {
            float w0 = Ws[          u * 32 + lane];
            float w1 = Ws[1024 +    u * 32 + lane];
            float w2 = Ws[2048 +    u * 32 + lane];
            float w3 = Ws[3072 +    u * 32 + lane];
            float w4 = Ws[4096 +    u * 32 + lane];
            #pragma unroll
            for (int nn = 0; nn < NPW; nn++) {
                float4 v = xs[wl][nn * 32 + u];   // broadcast (all lanes same addr)
                a1[nn] = fmaf(v.x, w0, a1[nn]);
                a2[nn] = fmaf(v.x, w1, a2[nn]);
                b3[nn][0] = fmaf(v.y, w2, b3[nn][0]);
                b3[nn][1] = fmaf(v.z, w2, b3[nn][1]);
                b3[nn][2] = fmaf(v.w, w2, b3[nn][2]);
                b4[nn][0] = fmaf(v.y, w3, b4[nn][0]);
                b4[nn][1] = fmaf(v.z, w3, b4[nn][1]);
                b4[nn][2] = fmaf(v.w, w3, b4[nn][2]);
                b5[nn][0] = fmaf(v.y, w4, b5[nn][0]);
                b5[nn][1] = fmaf(v.z, w4, b5[nn][1]);
                b5[nn][2] = fmaf(v.w, w4, b5[nn][2]);
            }
        }

        #pragma unroll
        for (int nn = 0; nn < NPW; nn++) {
            int n = nb + nn;
            if (n >= n_nodes) break;
            float c30 = b3[nn][0] * D0, c31 = b3[nn][1] * D1, c32 = b3[nn][2] * D0;
            float c40 = b4[nn][0] * E0, c41 = b4[nn][1] * E1, c42 = b4[nn][2] * E0;
            uint4 p;
            p.x = pack2(a1[nn], a2[nn]);
            p.y = pack2(c30, c31);
            p.z = pack2(c32, c40);
            p.w = pack2(c41, c42);
            uint2 q;
            q.x = pack2(b5[nn][0], b5[nn][1]);
            q.y = pack2(b5[nn][2], 0.f);
            g_node4[n * 32 + lane] = p;
            g_node2[n * 32 + lane] = q;
        }
        __syncwarp();
    }
}

// ---------------- per-edge: fp16 record gather, SMEM-staged transpose, red.v4 ----------------
__global__ void __launch_bounds__(256) edge_kernel(const float* __restrict__ sh,
                                                   const int* __restrict__ eidx,
                                                   float* __restrict__ out,
                                                   int n_edges) {
    __shared__ __align__(16) float buf[8][128];
    const unsigned FULL = 0xFFFFFFFFu;
    int lane  = threadIdx.x & 31;
    int wl    = threadIdx.x >> 5;
    int warp  = (blockIdx.x * blockDim.x + threadIdx.x) >> 5;
    int nwarp = (gridDim.x * blockDim.x) >> 5;
    float* b = buf[wl];

    int e = warp;
    int src = 0, dst = 0;
    float sv = 0.f;
    if (e < n_edges) {
        src = eidx[e];
        dst = eidx[n_edges + e];
        sv  = (lane < 9) ? sh[(size_t)e * 9 + lane] : 0.f;
    }

    while (e < n_edges) {
        // issue record gather first (longest latency)
        uint4 rp = g_node4[src * 32 + lane];
        uint2 rq = g_node2[src * 32 + lane];

        // prefetch next edge's idx + sh while the gather is in flight
        int en = e + nwarp;
        int nsrc = 0, ndst = 0;
        float nsv = 0.f;
        if (en < n_edges) {
            nsrc = eidx[en];
            ndst = eidx[n_edges + en];
            nsv  = (lane < 9) ? sh[(size_t)en * 9 + lane] : 0.f;
        }

        // broadcast sh components
        float s0  = __shfl_sync(FULL, sv, 0);
        float s1x = __shfl_sync(FULL, sv, 1);
        float s1y = __shfl_sync(FULL, sv, 2);
        float s1z = __shfl_sync(FULL, sv, 3);
        float q0  = __shfl_sync(FULL, sv, 4);
        float q1v = __shfl_sync(FULL, sv, 5);
        float q2  = __shfl_sync(FULL, sv, 6);
        float q3  = __shfl_sync(FULL, sv, 7);
        float q4  = __shfl_sync(FULL, sv, 8);

        // path (1,2,1) sh-contraction terms
        float n2q2 = N2 * q2;
        float n1q4 = N1 * q4;
        float n1q0 = N1 * q0;
        float n3q1 = N3 * q1v;
        float n4q1 = N4 * q1v;
        float n3q3 = N3 * q3;
        float n4q3 = N4 * q3;

        float2 u0 = unpack2(rp.x);   // a1, a2
        float2 u1 = unpack2(rp.y);   // b3x, b3y
        float2 u2 = unpack2(rp.z);   // b3z, b4x
        float2 u3 = unpack2(rp.w);   // b4y, b4z
        float2 u4 = unpack2(rq.x);   // b5x, b5y
        float2 u5 = unpack2(rq.y);   // b5z, -
        float a1 = u0.x, a2 = u0.y;
        float b3x = u1.x, b3y = u1.y, b3z = u2.x;
        float b4x = u2.y, b4y = u3.x, b4z = u3.y;
        float b5x = u4.x, b5y = u4.y, b5z = u5.x;

        // out0: paths (0,0,0) and (1,1,0)
        float m0 = s0 * a1;
        m0 = fmaf(s1x, b4x, m0);
        m0 = fmaf(s1y, b4y, m0);
        m0 = fmaf(s1z, b4z, m0);

        // out1: paths (0,1,1), (1,0,1), (1,2,1)
        float m1x = fmaf(D0 * s1x, a2,
                    fmaf(s0, b3x,
                    fmaf(-(n2q2 + n1q4), b5x,
                    fmaf(n3q1, b5y, n1q0 * b5z))));
        float m1y = fmaf(D1 * s1y, a2,
                    fmaf(s0, b3y,
                    fmaf(n4q1, b5x,
                    fmaf(n2q2, b5y, n4q3 * b5z))));
        float m1z = fmaf(D0 * s1z, a2,
                    fmaf(s0, b3z,
                    fmaf(n1q0, b5x,
                    fmaf(n3q3, b5y, (n1q4 - n2q2) * b5z))));

        // SMEM-staged transpose (conflict-free: stride 3 coprime with 32 banks)
        b[lane]              = m0;
        b[32 + 3 * lane + 0] = m1x;
        b[32 + 3 * lane + 1] = m1y;
        b[32 + 3 * lane + 2] = m1z;
        __syncwarp();
        float4 v4 = *reinterpret_cast<float4*>(b + 4 * lane);
        float* dptr = out + (size_t)dst * 128 + 4 * lane;
        asm volatile("red.global.add.v4.f32 [%0], {%1,%2,%3,%4};"
                     :: "l"(dptr), "f"(v4.x), "f"(v4.y), "f"(v4.z), "f"(v4.w) : "memory");
        __syncwarp();

        e = en; src = nsrc; dst = ndst; sv = nsv;
    }
}

// ---------------- launch ----------------
extern "C" void kernel_launch(void* const* d_in, const int* in_sizes, int n_in,
                              void* d_out, int out_size) {
    const float* feat = (const float*)d_in[0];
    const float* sh   = (const float*)d_in[1];
    const int*   eidx = (const int*)d_in[2];
    const float* W    = (const float*)d_in[3];
    int n_nodes = in_sizes[0] / 128;
    int n_edges = in_sizes[2] / 2;

    cudaMemsetAsync(d_out, 0, (size_t)out_size * sizeof(float));

    int warps_needed = (n_nodes + NPW - 1) / NPW;
    int pre_blocks = (warps_needed + 7) / 8;
    precompute_kernel<<<pre_blocks, 256>>>(feat, W, n_nodes);
    edge_kernel<<<2048, 256>>>(sh, eidx, (float*)d_out, n_edges);
}